// round 15
// baseline (speedup 1.0000x reference)
#include <cuda_runtime.h>
#include <cuda_fp16.h>
#include <cstdint>

// Problem sizes
#define Nz 16384
#define Dd 256
#define Kk 1024

// GEMM tiling (champion config)
#define BM 128
#define BN 128
#define BK 32                    // k floats per chunk
#define NCH (Dd / BK)            // 8 k-chunks
#define TSTR 40                  // smem row stride in halves (conflict-free ldmatrix)
#define T_H  (128 * TSTR)        // tile size in halves (5120)
#define STG_H (4 * T_H)          // stage: Azh, Azl, Bch, Bcl
#define SMEM_BYTES (2 * STG_H * 2)   // 2 stages = 81920 B

// ---------------- device scratch ----------------
__device__ __align__(16) __half g_zh[Nz * Dd];
__device__ __align__(16) __half g_zl[Nz * Dd];
__device__ __align__(16) __half g_ch[Kk * Dd];
__device__ __align__(16) __half g_cl[Kk * Dd];
__device__ __align__(16) float  g_csq[Kk];
__device__ __align__(16) float  g_dot[(size_t)Nz * Kk];   // stores LOGITS (10*dot-5*csq)
__device__ __align__(16) float  g_counts[Kk];
__device__ __align__(16) float  g_dw[Kk * Dd];

// ---------------- helpers ----------------
__device__ __forceinline__ uint32_t smem_u32(const void* p) {
    uint32_t a;
    asm("{ .reg .u64 t; cvta.to.shared.u64 t, %1; cvt.u32.u64 %0, t; }" : "=r"(a) : "l"(p));
    return a;
}
__device__ __forceinline__ void cp16(uint32_t dst, const void* src) {
    asm volatile("cp.async.cg.shared.global [%0], [%1], 16;" :: "r"(dst), "l"(src));
}
__device__ __forceinline__ void ldsm4(uint32_t* r, uint32_t a) {
    asm volatile("ldmatrix.sync.aligned.m8n8.x4.shared.b16 {%0,%1,%2,%3}, [%4];"
                 : "=r"(r[0]), "=r"(r[1]), "=r"(r[2]), "=r"(r[3]) : "r"(a));
}
__device__ __forceinline__ void mma_f16(float* d, const uint32_t* a, const uint32_t* b) {
    asm volatile(
        "mma.sync.aligned.m16n8k16.row.col.f32.f16.f16.f32 "
        "{%0,%1,%2,%3}, {%4,%5,%6,%7}, {%8,%9}, {%0,%1,%2,%3};"
        : "+f"(d[0]), "+f"(d[1]), "+f"(d[2]), "+f"(d[3])
        : "r"(a[0]), "r"(a[1]), "r"(a[2]), "r"(a[3]), "r"(b[0]), "r"(b[1]));
}

// ---------------------------------------------------------------------------
// Combined split kernel:
//   blocks [0, 4096)     : z -> fp16 hi/lo (vectorized)
//   blocks [4096, 5120)  : centroids -> hi/lo, csq, zero dw/counts
// (softmax is shift-invariant: -5*zsq row constant dropped everywhere)
// ---------------------------------------------------------------------------
__global__ void split_kernel(const float* __restrict__ z, const float* __restrict__ cent) {
    const int b = blockIdx.x, t = threadIdx.x;
    if (b < 4096) {
        int idx = b * 256 + t;                         // over Nz*Dd/4
        float4 v = reinterpret_cast<const float4*>(z)[idx];
        __half hx = __float2half(v.x), hy = __float2half(v.y);
        __half hz = __float2half(v.z), hw = __float2half(v.w);
        __half lx = __float2half(v.x - __half2float(hx));
        __half ly = __float2half(v.y - __half2float(hy));
        __half lz = __float2half(v.z - __half2float(hz));
        __half lw = __float2half(v.w - __half2float(hw));
        reinterpret_cast<half2*>(g_zh)[idx * 2]     = __halves2half2(hx, hy);
        reinterpret_cast<half2*>(g_zh)[idx * 2 + 1] = __halves2half2(hz, hw);
        reinterpret_cast<half2*>(g_zl)[idx * 2]     = __halves2half2(lx, ly);
        reinterpret_cast<half2*>(g_zl)[idx * 2 + 1] = __halves2half2(lz, lw);
    } else {
        int k = b - 4096;
        int i = k * Dd + t;
        float v = cent[i];
        __half h = __float2half(v);
        __half l = __float2half(v - __half2float(h));
        g_ch[i] = h;
        g_cl[i] = l;
        g_dw[i] = 0.f;

        float s = v * v;
        #pragma unroll
        for (int o = 16; o > 0; o >>= 1) s += __shfl_down_sync(0xffffffffu, s, o);
        __shared__ float red[8];
        if ((t & 31) == 0) red[t >> 5] = s;
        __syncthreads();
        if (t == 0) {
            float x = 0.f;
            #pragma unroll
            for (int j = 0; j < 8; j++) x += red[j];
            g_csq[k]    = x;
            g_counts[k] = 0.f;
        }
    }
}

// ---------------------------------------------------------------------------
// Stage one K-chunk: Azh, Azl (128x32h) + Bch, Bcl (128x32h) via cp.async
// ---------------------------------------------------------------------------
__device__ __forceinline__ void stage_chunk(uint32_t su, int s, int kc,
                                            int row0, int col0, int tid) {
    const int koff = kc * BK;                      // halves
    const uint32_t sb = su + (uint32_t)(s * STG_H) * 2u;
    #pragma unroll
    for (int i = 0; i < 2; i++) {
        int idx = i * 256 + tid;                   // 0..511
        int r = idx >> 2, grp = idx & 3;           // row 0..127, 16B group 0..3
        uint32_t d = (uint32_t)(r * TSTR + grp * 8) * 2u;
        const __half* az = g_zh + (size_t)(row0 + r) * Dd + koff + grp * 8;
        const __half* al = g_zl + (size_t)(row0 + r) * Dd + koff + grp * 8;
        const __half* bc = g_ch + (size_t)(col0 + r) * Dd + koff + grp * 8;
        const __half* bl = g_cl + (size_t)(col0 + r) * Dd + koff + grp * 8;
        cp16(sb + d,                      az);
        cp16(sb + (uint32_t)T_H * 2u + d, al);
        cp16(sb + (uint32_t)T_H * 4u + d, bc);
        cp16(sb + (uint32_t)T_H * 6u + d, bl);
    }
    asm volatile("cp.async.commit_group;" ::: "memory");
}

// ---------------------------------------------------------------------------
// fp16x3 GEMM: logits = 10*(z@C^T) - 5*csq, via zh.ch + zl.ch + zh.cl
// 1024 CTAs, 256 threads, 2-stage cp.async, warp tile 32x64, ldmatrix operands
// ---------------------------------------------------------------------------
__global__ void __launch_bounds__(256, 2) gemm_kernel() {
    extern __shared__ __half sm[];
    const int tid  = threadIdx.x;
    const int w    = tid >> 5;
    const int lane = tid & 31;
    const int wm   = w >> 1;        // 0..3 (M)
    const int wn   = w & 1;         // 0..1 (N)
    const int mt   = blockIdx.x >> 3, nt = blockIdx.x & 7;
    const int row0 = mt * BM, col0 = nt * BN;
    const int mbase = wm * 32, nbase = wn * 64;

    const uint32_t su = smem_u32(sm);

    // ldmatrix per-lane address offsets (bytes within a tile)
    const uint32_t aoff = (uint32_t)((mbase + (lane & 15)) * TSTR + (lane >> 4) * 8) * 2u;
    const int r8 = lane & 7, sel = lane >> 3;
    const uint32_t boff = (uint32_t)((nbase + (sel >> 1) * 8 + r8) * TSTR + (sel & 1) * 8) * 2u;

    float acc[2][8][4];
    #pragma unroll
    for (int i = 0; i < 2; i++)
        #pragma unroll
        for (int j = 0; j < 8; j++)
            #pragma unroll
            for (int q = 0; q < 4; q++) acc[i][j][q] = 0.f;

    stage_chunk(su, 0, 0, row0, col0, tid);
    stage_chunk(su, 1, 1, row0, col0, tid);

    #pragma unroll 1
    for (int kc = 0; kc < NCH; kc++) {
        const int s = kc & 1;
        if (kc < NCH - 1) asm volatile("cp.async.wait_group 1;" ::: "memory");
        else              asm volatile("cp.async.wait_group 0;" ::: "memory");
        __syncthreads();

        const uint32_t Ah = su + (uint32_t)(s * STG_H) * 2u;
        const uint32_t Al = Ah + (uint32_t)T_H * 2u;
        const uint32_t Bh = Ah + (uint32_t)T_H * 4u;
        const uint32_t Bl = Ah + (uint32_t)T_H * 6u;

        #pragma unroll
        for (int kq = 0; kq < 2; kq++) {
            const uint32_t kb = (uint32_t)kq * 32u;      // 16 halves = 32 bytes
            uint32_t ah[2][4], al[2][4], bh[8][2], bl[8][2];
            #pragma unroll
            for (int i = 0; i < 2; i++) {
                const uint32_t d = aoff + (uint32_t)(i * 16 * TSTR) * 2u + kb;
                ldsm4(ah[i], Ah + d);
                ldsm4(al[i], Al + d);
            }
            #pragma unroll
            for (int p = 0; p < 4; p++) {
                const uint32_t d = boff + (uint32_t)(p * 16 * TSTR) * 2u + kb;
                ldsm4(&bh[2 * p][0], Bh + d);   // fills bh[2p], bh[2p+1]
                ldsm4(&bl[2 * p][0], Bl + d);
            }
            #pragma unroll
            for (int i = 0; i < 2; i++)
                #pragma unroll
                for (int j = 0; j < 8; j++) {
                    mma_f16(acc[i][j], ah[i], bh[j]);   // zh . ch
                    mma_f16(acc[i][j], al[i], bh[j]);   // zl . ch
                    mma_f16(acc[i][j], ah[i], bl[j]);   // zh . cl
                }
        }
        __syncthreads();
        if (kc + 2 < NCH) stage_chunk(su, s, kc + 2, row0, col0, tid);
    }

    // Epilogue: logits = 10*acc - 5*csq[col]
    const int g  = lane >> 2;
    const int tg = lane & 3;
    #pragma unroll
    for (int i = 0; i < 2; i++) {
        const size_t r0 = (size_t)(row0 + mbase + i * 16 + g);
        #pragma unroll
        for (int j = 0; j < 8; j++) {
            const int col = col0 + nbase + j * 8 + 2 * tg;
            float2 cs = *reinterpret_cast<const float2*>(g_csq + col);
            float2 v0 = make_float2(fmaf(10.f, acc[i][j][0], -5.f * cs.x),
                                    fmaf(10.f, acc[i][j][1], -5.f * cs.y));
            float2 v1 = make_float2(fmaf(10.f, acc[i][j][2], -5.f * cs.x),
                                    fmaf(10.f, acc[i][j][3], -5.f * cs.y));
            *reinterpret_cast<float2*>(g_dot + r0 * Kk + col)       = v0;
            *reinterpret_cast<float2*>(g_dot + (r0 + 8) * Kk + col) = v1;
        }
    }
}

// ---------------------------------------------------------------------------
// Phase 2: ONE BLOCK PER ROW (grid = 16384, 256 threads), REVERSE row order:
// highest rows were written to L2 most recently by the GEMM -> read them first
// while still resident. Per-row math identical to champion.
// ---------------------------------------------------------------------------
__global__ void __launch_bounds__(256) softmax_kernel(const float* __restrict__ z,
                                                      const float* __restrict__ cent,
                                                      float* __restrict__ recons,
                                                      float* __restrict__ gamma) {
    const int row  = Nz - 1 - blockIdx.x;          // reverse order for L2 locality
    const int t    = threadIdx.x;
    const int lane = t & 31, w = t >> 5;

    __shared__ float sm_m[8];
    __shared__ int   sm_i[8];
    __shared__ float sm_s[8];
    __shared__ float sh_m, sh_inv;
    __shared__ int   sh_mi;

    const float4 v = __ldg(reinterpret_cast<const float4*>(g_dot + (size_t)row * Kk) + t);

    // per-thread max + first-index (ascending cols 4t..4t+3)
    float m = v.x; int mi = 4 * t;
    if (v.y > m) { m = v.y; mi = 4 * t + 1; }
    if (v.z > m) { m = v.z; mi = 4 * t + 2; }
    if (v.w > m) { m = v.w; mi = 4 * t + 3; }
    #pragma unroll
    for (int o = 16; o > 0; o >>= 1) {
        float om = __shfl_xor_sync(0xffffffffu, m,  o);
        int   oi = __shfl_xor_sync(0xffffffffu, mi, o);
        if (om > m || (om == m && oi < mi)) { m = om; mi = oi; }
    }
    if (lane == 0) { sm_m[w] = m; sm_i[w] = mi; }
    __syncthreads();
    if (t < 32) {
        float mm = (t < 8) ? sm_m[t] : -1e30f;
        int   ii = (t < 8) ? sm_i[t] : 0x7fffffff;
        #pragma unroll
        for (int o = 4; o > 0; o >>= 1) {
            float om = __shfl_xor_sync(0xffffffffu, mm, o);
            int   oi = __shfl_xor_sync(0xffffffffu, ii, o);
            if (om > mm || (om == mm && oi < ii)) { mm = om; ii = oi; }
        }
        if (t == 0) { sh_m = mm; sh_mi = ii; }
    }
    __syncthreads();
    m = sh_m;
    const int kstar = sh_mi;

    // exp + block sum
    float4 e;
    e.x = __expf(v.x - m); e.y = __expf(v.y - m);
    e.z = __expf(v.z - m); e.w = __expf(v.w - m);
    float s = e.x + e.y + e.z + e.w;
    #pragma unroll
    for (int o = 16; o > 0; o >>= 1) s += __shfl_xor_sync(0xffffffffu, s, o);
    if (lane == 0) sm_s[w] = s;
    __syncthreads();
    if (t < 32) {
        float ss = (t < 8) ? sm_s[t] : 0.f;
        #pragma unroll
        for (int o = 4; o > 0; o >>= 1) ss += __shfl_xor_sync(0xffffffffu, ss, o);
        if (t == 0) sh_inv = 1.f / ss;
    }
    __syncthreads();
    const float inv = sh_inv;

    float4 gv = make_float4(e.x * inv, e.y * inv, e.z * inv, e.w * inv);
    __stcs(reinterpret_cast<float4*>(gamma + (size_t)row * Kk) + t, gv);

    const float zv = __ldg(z    + (size_t)row   * Dd + t);
    const float cv = __ldg(cent + (size_t)kstar * Dd + t);
    __stcs(recons + (size_t)row * Dd + t, zv + (cv - zv));
    atomicAdd(g_dw + (size_t)kstar * Dd + t, zv);
    if (t == 0) atomicAdd(&g_counts[kstar], 1.f);
}

// ---------------------------------------------------------------------------
// Finalize with fused EMA-size normalization; 4 centroids per block so the
// redundant counts reduction is amortized (grid 256).
// ---------------------------------------------------------------------------
__global__ void __launch_bounds__(256) finalize_kernel(const float* __restrict__ ema_w,
                                                       const float* __restrict__ ema_cs,
                                                       float* __restrict__ out) {
    const int t = threadIdx.x;
    const int lane = t & 31, w = t >> 5;
    __shared__ float red[8];
    __shared__ float n_sh;

    // n = sum_j (ema_cs[j]*0.95 + 0.05*counts[j])
    float p = 0.f;
    #pragma unroll
    for (int j = 0; j < 4; j++) {
        int idx = t + j * 256;
        p += ema_cs[idx] * 0.95f + 0.05f * g_counts[idx];
    }
    #pragma unroll
    for (int o = 16; o > 0; o >>= 1) p += __shfl_down_sync(0xffffffffu, p, o);
    if (lane == 0) red[w] = p;
    __syncthreads();
    if (t == 0) {
        float x = 0.f;
        #pragma unroll
        for (int j = 0; j < 8; j++) x += red[j];
        n_sh = x;
    }
    __syncthreads();
    const float n = n_sh;

    const int kbase = blockIdx.x * 4;
    #pragma unroll
    for (int q = 0; q < 4; q++) {
        const int k = kbase + q;
        const float ncs_k = ema_cs[k] * 0.95f + 0.05f * g_counts[k];
        const float ncs = (ncs_k + 1e-5f) / (n + 0.01024f) * n;   // (cs+eps)/(n+K*eps)*n
        const size_t i = (size_t)k * Dd + t;
        out[i] = (ema_w[i] * 0.95f + 0.05f * g_dw[i]) / ncs;
    }
}

// ---------------------------------------------------------------------------
extern "C" void kernel_launch(void* const* d_in, const int* in_sizes, int n_in,
                              void* d_out, int out_size) {
    const float* z      = (const float*)d_in[0];
    const float* cent   = (const float*)d_in[1];
    const float* ema_w  = (const float*)d_in[2];
    const float* ema_cs = (const float*)d_in[3];

    float* out    = (float*)d_out;
    float* recons = out;
    float* gamma  = out + (size_t)Nz * Dd;
    float* newc   = out + (size_t)Nz * Dd + (size_t)Nz * Kk;

    cudaFuncSetAttribute(gemm_kernel, cudaFuncAttributeMaxDynamicSharedMemorySize, SMEM_BYTES);

    split_kernel<<<4096 + 1024, 256>>>(z, cent);
    gemm_kernel<<<(Nz / BM) * (Kk / BN), 256, SMEM_BYTES>>>();
    softmax_kernel<<<Nz, 256>>>(z, cent, recons, gamma);
    finalize_kernel<<<Kk / 4, 256>>>(ema_w, ema_cs, newc);
}

// round 16
// speedup vs baseline: 1.0128x; 1.0128x over previous
#include <cuda_runtime.h>
#include <cuda_fp16.h>
#include <cstdint>

// Problem sizes
#define Nz 16384
#define Dd 256
#define Kk 1024

// GEMM tiling (champion config)
#define BM 128
#define BN 128
#define BK 32                    // k floats per chunk
#define NCH (Dd / BK)            // 8 k-chunks
#define TSTR 40                  // smem row stride in halves (conflict-free ldmatrix)
#define T_H  (128 * TSTR)        // tile size in halves (5120)
#define STG_H (4 * T_H)          // stage: Azh, Azl, Bch, Bcl
#define SMEM_BYTES (2 * STG_H * 2)   // 2 stages = 81920 B

// ---------------- device scratch ----------------
__device__ __align__(16) __half g_zh[Nz * Dd];
__device__ __align__(16) __half g_zl[Nz * Dd];
__device__ __align__(16) __half g_ch[Kk * Dd];
__device__ __align__(16) __half g_cl[Kk * Dd];
__device__ __align__(16) float  g_csq[Kk];
__device__ __align__(16) float  g_dot[(size_t)Nz * Kk];   // stores LOGITS (10*dot-5*csq)
__device__ __align__(16) float  g_counts[Kk];
__device__ __align__(16) float  g_dw[Kk * Dd];

// ---------------- helpers ----------------
__device__ __forceinline__ uint32_t smem_u32(const void* p) {
    uint32_t a;
    asm("{ .reg .u64 t; cvta.to.shared.u64 t, %1; cvt.u32.u64 %0, t; }" : "=r"(a) : "l"(p));
    return a;
}
__device__ __forceinline__ void cp16(uint32_t dst, const void* src) {
    asm volatile("cp.async.cg.shared.global [%0], [%1], 16;" :: "r"(dst), "l"(src));
}
__device__ __forceinline__ void ldsm4(uint32_t* r, uint32_t a) {
    asm volatile("ldmatrix.sync.aligned.m8n8.x4.shared.b16 {%0,%1,%2,%3}, [%4];"
                 : "=r"(r[0]), "=r"(r[1]), "=r"(r[2]), "=r"(r[3]) : "r"(a));
}
__device__ __forceinline__ void mma_f16(float* d, const uint32_t* a, const uint32_t* b) {
    asm volatile(
        "mma.sync.aligned.m16n8k16.row.col.f32.f16.f16.f32 "
        "{%0,%1,%2,%3}, {%4,%5,%6,%7}, {%8,%9}, {%0,%1,%2,%3};"
        : "+f"(d[0]), "+f"(d[1]), "+f"(d[2]), "+f"(d[3])
        : "r"(a[0]), "r"(a[1]), "r"(a[2]), "r"(a[3]), "r"(b[0]), "r"(b[1]));
}

// ---------------------------------------------------------------------------
// Combined split kernel:
//   blocks [0, 4096)     : z -> fp16 hi/lo (vectorized)
//   blocks [4096, 5120)  : centroids -> hi/lo, csq, zero dw/counts
// (softmax is shift-invariant: -5*zsq row constant dropped everywhere)
// ---------------------------------------------------------------------------
__global__ void split_kernel(const float* __restrict__ z, const float* __restrict__ cent) {
    const int b = blockIdx.x, t = threadIdx.x;
    if (b < 4096) {
        int idx = b * 256 + t;                         // over Nz*Dd/4
        float4 v = reinterpret_cast<const float4*>(z)[idx];
        __half hx = __float2half(v.x), hy = __float2half(v.y);
        __half hz = __float2half(v.z), hw = __float2half(v.w);
        __half lx = __float2half(v.x - __half2float(hx));
        __half ly = __float2half(v.y - __half2float(hy));
        __half lz = __float2half(v.z - __half2float(hz));
        __half lw = __float2half(v.w - __half2float(hw));
        reinterpret_cast<half2*>(g_zh)[idx * 2]     = __halves2half2(hx, hy);
        reinterpret_cast<half2*>(g_zh)[idx * 2 + 1] = __halves2half2(hz, hw);
        reinterpret_cast<half2*>(g_zl)[idx * 2]     = __halves2half2(lx, ly);
        reinterpret_cast<half2*>(g_zl)[idx * 2 + 1] = __halves2half2(lz, lw);
    } else {
        int k = b - 4096;
        int i = k * Dd + t;
        float v = cent[i];
        __half h = __float2half(v);
        __half l = __float2half(v - __half2float(h));
        g_ch[i] = h;
        g_cl[i] = l;
        g_dw[i] = 0.f;

        float s = v * v;
        #pragma unroll
        for (int o = 16; o > 0; o >>= 1) s += __shfl_down_sync(0xffffffffu, s, o);
        __shared__ float red[8];
        if ((t & 31) == 0) red[t >> 5] = s;
        __syncthreads();
        if (t == 0) {
            float x = 0.f;
            #pragma unroll
            for (int j = 0; j < 8; j++) x += red[j];
            g_csq[k]    = x;
            g_counts[k] = 0.f;
        }
    }
}

// ---------------------------------------------------------------------------
// Stage one K-chunk: Azh, Azl (128x32h) + Bch, Bcl (128x32h) via cp.async
// ---------------------------------------------------------------------------
__device__ __forceinline__ void stage_chunk(uint32_t su, int s, int kc,
                                            int row0, int col0, int tid) {
    const int koff = kc * BK;                      // halves
    const uint32_t sb = su + (uint32_t)(s * STG_H) * 2u;
    #pragma unroll
    for (int i = 0; i < 2; i++) {
        int idx = i * 256 + tid;                   // 0..511
        int r = idx >> 2, grp = idx & 3;           // row 0..127, 16B group 0..3
        uint32_t d = (uint32_t)(r * TSTR + grp * 8) * 2u;
        const __half* az = g_zh + (size_t)(row0 + r) * Dd + koff + grp * 8;
        const __half* al = g_zl + (size_t)(row0 + r) * Dd + koff + grp * 8;
        const __half* bc = g_ch + (size_t)(col0 + r) * Dd + koff + grp * 8;
        const __half* bl = g_cl + (size_t)(col0 + r) * Dd + koff + grp * 8;
        cp16(sb + d,                      az);
        cp16(sb + (uint32_t)T_H * 2u + d, al);
        cp16(sb + (uint32_t)T_H * 4u + d, bc);
        cp16(sb + (uint32_t)T_H * 6u + d, bl);
    }
    asm volatile("cp.async.commit_group;" ::: "memory");
}

// ---------------------------------------------------------------------------
// fp16x3 GEMM: logits = 10*(z@C^T) - 5*csq, via zh.ch + zl.ch + zh.cl
// 1024 CTAs, 256 threads, 2-stage cp.async, warp tile 32x64, ldmatrix operands
// ---------------------------------------------------------------------------
__global__ void __launch_bounds__(256, 2) gemm_kernel() {
    extern __shared__ __half sm[];
    const int tid  = threadIdx.x;
    const int w    = tid >> 5;
    const int lane = tid & 31;
    const int wm   = w >> 1;        // 0..3 (M)
    const int wn   = w & 1;         // 0..1 (N)
    const int mt   = blockIdx.x >> 3, nt = blockIdx.x & 7;
    const int row0 = mt * BM, col0 = nt * BN;
    const int mbase = wm * 32, nbase = wn * 64;

    const uint32_t su = smem_u32(sm);

    // ldmatrix per-lane address offsets (bytes within a tile)
    const uint32_t aoff = (uint32_t)((mbase + (lane & 15)) * TSTR + (lane >> 4) * 8) * 2u;
    const int r8 = lane & 7, sel = lane >> 3;
    const uint32_t boff = (uint32_t)((nbase + (sel >> 1) * 8 + r8) * TSTR + (sel & 1) * 8) * 2u;

    float acc[2][8][4];
    #pragma unroll
    for (int i = 0; i < 2; i++)
        #pragma unroll
        for (int j = 0; j < 8; j++)
            #pragma unroll
            for (int q = 0; q < 4; q++) acc[i][j][q] = 0.f;

    stage_chunk(su, 0, 0, row0, col0, tid);
    stage_chunk(su, 1, 1, row0, col0, tid);

    #pragma unroll 1
    for (int kc = 0; kc < NCH; kc++) {
        const int s = kc & 1;
        if (kc < NCH - 1) asm volatile("cp.async.wait_group 1;" ::: "memory");
        else              asm volatile("cp.async.wait_group 0;" ::: "memory");
        __syncthreads();

        const uint32_t Ah = su + (uint32_t)(s * STG_H) * 2u;
        const uint32_t Al = Ah + (uint32_t)T_H * 2u;
        const uint32_t Bh = Ah + (uint32_t)T_H * 4u;
        const uint32_t Bl = Ah + (uint32_t)T_H * 6u;

        #pragma unroll
        for (int kq = 0; kq < 2; kq++) {
            const uint32_t kb = (uint32_t)kq * 32u;      // 16 halves = 32 bytes
            uint32_t ah[2][4], al[2][4], bh[8][2], bl[8][2];
            #pragma unroll
            for (int i = 0; i < 2; i++) {
                const uint32_t d = aoff + (uint32_t)(i * 16 * TSTR) * 2u + kb;
                ldsm4(ah[i], Ah + d);
                ldsm4(al[i], Al + d);
            }
            #pragma unroll
            for (int p = 0; p < 4; p++) {
                const uint32_t d = boff + (uint32_t)(p * 16 * TSTR) * 2u + kb;
                ldsm4(&bh[2 * p][0], Bh + d);   // fills bh[2p], bh[2p+1]
                ldsm4(&bl[2 * p][0], Bl + d);
            }
            #pragma unroll
            for (int i = 0; i < 2; i++)
                #pragma unroll
                for (int j = 0; j < 8; j++) {
                    mma_f16(acc[i][j], ah[i], bh[j]);   // zh . ch
                    mma_f16(acc[i][j], al[i], bh[j]);   // zl . ch
                    mma_f16(acc[i][j], ah[i], bl[j]);   // zh . cl
                }
        }
        __syncthreads();
        if (kc + 2 < NCH) stage_chunk(su, s, kc + 2, row0, col0, tid);
    }

    // Epilogue: logits = 10*acc - 5*csq[col]
    const int g  = lane >> 2;
    const int tg = lane & 3;
    #pragma unroll
    for (int i = 0; i < 2; i++) {
        const size_t r0 = (size_t)(row0 + mbase + i * 16 + g);
        #pragma unroll
        for (int j = 0; j < 8; j++) {
            const int col = col0 + nbase + j * 8 + 2 * tg;
            float2 cs = *reinterpret_cast<const float2*>(g_csq + col);
            float2 v0 = make_float2(fmaf(10.f, acc[i][j][0], -5.f * cs.x),
                                    fmaf(10.f, acc[i][j][1], -5.f * cs.y));
            float2 v1 = make_float2(fmaf(10.f, acc[i][j][2], -5.f * cs.x),
                                    fmaf(10.f, acc[i][j][3], -5.f * cs.y));
            *reinterpret_cast<float2*>(g_dot + r0 * Kk + col)       = v0;
            *reinterpret_cast<float2*>(g_dot + (r0 + 8) * Kk + col) = v1;
        }
    }
}

// ---------------------------------------------------------------------------
// Phase 2: ONE BLOCK PER ROW (grid = 16384, 256 threads), REVERSE row order:
// highest rows were written to L2 most recently by the GEMM -> read them first
// while still resident. Per-row math identical to champion.
// ---------------------------------------------------------------------------
__global__ void __launch_bounds__(256) softmax_kernel(const float* __restrict__ z,
                                                      const float* __restrict__ cent,
                                                      float* __restrict__ recons,
                                                      float* __restrict__ gamma) {
    const int row  = Nz - 1 - blockIdx.x;          // reverse order for L2 locality
    const int t    = threadIdx.x;
    const int lane = t & 31, w = t >> 5;

    __shared__ float sm_m[8];
    __shared__ int   sm_i[8];
    __shared__ float sm_s[8];
    __shared__ float sh_m, sh_inv;
    __shared__ int   sh_mi;

    const float4 v = __ldg(reinterpret_cast<const float4*>(g_dot + (size_t)row * Kk) + t);

    // per-thread max + first-index (ascending cols 4t..4t+3)
    float m = v.x; int mi = 4 * t;
    if (v.y > m) { m = v.y; mi = 4 * t + 1; }
    if (v.z > m) { m = v.z; mi = 4 * t + 2; }
    if (v.w > m) { m = v.w; mi = 4 * t + 3; }
    #pragma unroll
    for (int o = 16; o > 0; o >>= 1) {
        float om = __shfl_xor_sync(0xffffffffu, m,  o);
        int   oi = __shfl_xor_sync(0xffffffffu, mi, o);
        if (om > m || (om == m && oi < mi)) { m = om; mi = oi; }
    }
    if (lane == 0) { sm_m[w] = m; sm_i[w] = mi; }
    __syncthreads();
    if (t < 32) {
        float mm = (t < 8) ? sm_m[t] : -1e30f;
        int   ii = (t < 8) ? sm_i[t] : 0x7fffffff;
        #pragma unroll
        for (int o = 4; o > 0; o >>= 1) {
            float om = __shfl_xor_sync(0xffffffffu, mm, o);
            int   oi = __shfl_xor_sync(0xffffffffu, ii, o);
            if (om > mm || (om == mm && oi < ii)) { mm = om; ii = oi; }
        }
        if (t == 0) { sh_m = mm; sh_mi = ii; }
    }
    __syncthreads();
    m = sh_m;
    const int kstar = sh_mi;

    // exp + block sum
    float4 e;
    e.x = __expf(v.x - m); e.y = __expf(v.y - m);
    e.z = __expf(v.z - m); e.w = __expf(v.w - m);
    float s = e.x + e.y + e.z + e.w;
    #pragma unroll
    for (int o = 16; o > 0; o >>= 1) s += __shfl_xor_sync(0xffffffffu, s, o);
    if (lane == 0) sm_s[w] = s;
    __syncthreads();
    if (t < 32) {
        float ss = (t < 8) ? sm_s[t] : 0.f;
        #pragma unroll
        for (int o = 4; o > 0; o >>= 1) ss += __shfl_xor_sync(0xffffffffu, ss, o);
        if (t == 0) sh_inv = 1.f / ss;
    }
    __syncthreads();
    const float inv = sh_inv;

    float4 gv = make_float4(e.x * inv, e.y * inv, e.z * inv, e.w * inv);
    __stcs(reinterpret_cast<float4*>(gamma + (size_t)row * Kk) + t, gv);

    const float zv = __ldg(z    + (size_t)row   * Dd + t);
    const float cv = __ldg(cent + (size_t)kstar * Dd + t);
    __stcs(recons + (size_t)row * Dd + t, zv + (cv - zv));
    atomicAdd(g_dw + (size_t)kstar * Dd + t, zv);
    if (t == 0) atomicAdd(&g_counts[kstar], 1.f);
}

// ---------------------------------------------------------------------------
// Finalize with fused EMA-size normalization (R11-proven grid-1024 form)
// ---------------------------------------------------------------------------
__global__ void __launch_bounds__(256) finalize_kernel(const float* __restrict__ ema_w,
                                                       const float* __restrict__ ema_cs,
                                                       float* __restrict__ out) {
    const int k = blockIdx.x, t = threadIdx.x;
    const int lane = t & 31, w = t >> 5;
    __shared__ float red[8];
    __shared__ float n_sh;

    // n = sum_j (ema_cs[j]*0.95 + 0.05*counts[j])
    float p = 0.f;
    #pragma unroll
    for (int j = 0; j < 4; j++) {
        int idx = t + j * 256;
        p += ema_cs[idx] * 0.95f + 0.05f * g_counts[idx];
    }
    #pragma unroll
    for (int o = 16; o > 0; o >>= 1) p += __shfl_down_sync(0xffffffffu, p, o);
    if (lane == 0) red[w] = p;
    __syncthreads();
    if (t == 0) {
        float x = 0.f;
        #pragma unroll
        for (int j = 0; j < 8; j++) x += red[j];
        n_sh = x;
    }
    __syncthreads();
    const float n = n_sh;

    const float ncs_k = ema_cs[k] * 0.95f + 0.05f * g_counts[k];
    const float ncs = (ncs_k + 1e-5f) / (n + 0.01024f) * n;   // (cs+eps)/(n+K*eps)*n
    const size_t i = (size_t)k * Dd + t;
    out[i] = (ema_w[i] * 0.95f + 0.05f * g_dw[i]) / ncs;
}

// ---------------------------------------------------------------------------
extern "C" void kernel_launch(void* const* d_in, const int* in_sizes, int n_in,
                              void* d_out, int out_size) {
    const float* z      = (const float*)d_in[0];
    const float* cent   = (const float*)d_in[1];
    const float* ema_w  = (const float*)d_in[2];
    const float* ema_cs = (const float*)d_in[3];

    float* out    = (float*)d_out;
    float* recons = out;
    float* gamma  = out + (size_t)Nz * Dd;
    float* newc   = out + (size_t)Nz * Dd + (size_t)Nz * Kk;

    cudaFuncSetAttribute(gemm_kernel, cudaFuncAttributeMaxDynamicSharedMemorySize, SMEM_BYTES);

    split_kernel<<<4096 + 1024, 256>>>(z, cent);
    gemm_kernel<<<(Nz / BM) * (Kk / BN), 256, SMEM_BYTES>>>();
    softmax_kernel<<<Nz, 256>>>(z, cent, recons, gamma);
    finalize_kernel<<<Kk, 256>>>(ema_w, ema_cs, newc);
}